// round 9
// baseline (speedup 1.0000x reference)
#include <cuda_runtime.h>
#include <cuda_bf16.h>
#include <cstdint>

// mma.sync bf16 3-pass flash attention; double-buffered K/V bf16 tiles with
// LDG-chunk prefetch interleaved into PV MMA stream. One barrier per tile.
// B=4,H=16,S=2048,D=128, scale folded into Q. Grid (16,64), 256 thr, 8 warps.

#define SEQ 2048
#define DD 128
#define BM 128
#define BN 64
#define NT (SEQ/BN)
#define NTH 256
#define SCALE_INV 3.125f

// smem: Q hi/lo 64KB, then 2 K/V buffers of 64KB each
#define SM_QHI 0
#define SM_QLO 32768
#define SM_KV  65536
#define KV_STRIDE 65536
#define OFF_KHI 0
#define OFF_KLO 16384
#define OFF_VHI 32768
#define OFF_VLO 49152
#define SM_TOTAL 196608   // 192KB

typedef uint32_t u32;

__device__ __forceinline__ u32 smem_u32(const void* p) {
    u32 a; asm("{ .reg .u64 t; cvta.to.shared.u64 t, %1; cvt.u32.u64 %0, t; }" : "=r"(a) : "l"(p));
    return a;
}

// Swizzled byte offset in [R rows][128 bf16] tile (8-row x 64-col 1KB atoms,
// panel-major col, SW128 in atom). rshift = log2(R/8).
__device__ __forceinline__ u32 swz(int row, int col, int rshift) {
    u32 atom   = (u32)((row >> 3) + ((col >> 6) << rshift));
    u32 coloff = ((u32)(col & 63) * 2u) ^ (((u32)row & 7u) << 4);
    return atom * 1024u + ((u32)row & 7u) * 128u + coloff;
}

__device__ __forceinline__ void split2(float a, float b, u32& hi, u32& lo) {
    unsigned short ha = __bfloat16_as_ushort(__float2bfloat16(a));
    unsigned short hb = __bfloat16_as_ushort(__float2bfloat16(b));
    float ra = a - __bfloat162float(__ushort_as_bfloat16(ha));
    float rb = b - __bfloat162float(__ushort_as_bfloat16(hb));
    unsigned short la = __bfloat16_as_ushort(__float2bfloat16(ra));
    unsigned short lb = __bfloat16_as_ushort(__float2bfloat16(rb));
    hi = ((u32)hb << 16) | ha;
    lo = ((u32)lb << 16) | la;
}

#define LDSM4(r, a) \
    asm volatile("ldmatrix.sync.aligned.m8n8.x4.shared.b16 {%0,%1,%2,%3}, [%4];" \
        : "=r"((r)[0]), "=r"((r)[1]), "=r"((r)[2]), "=r"((r)[3]) : "r"(a))
#define LDSM4T(r, a) \
    asm volatile("ldmatrix.sync.aligned.m8n8.x4.trans.shared.b16 {%0,%1,%2,%3}, [%4];" \
        : "=r"((r)[0]), "=r"((r)[1]), "=r"((r)[2]), "=r"((r)[3]) : "r"(a))
#define MMA(c, a, b0, b1) \
    asm volatile("mma.sync.aligned.m16n8k16.row.col.f32.bf16.bf16.f32 " \
        "{%0,%1,%2,%3}, {%4,%5,%6,%7}, {%8,%9}, {%0,%1,%2,%3};" \
        : "+f"((c)[0]), "+f"((c)[1]), "+f"((c)[2]), "+f"((c)[3]) \
        : "r"((a)[0]), "r"((a)[1]), "r"((a)[2]), "r"((a)[3]), "r"(b0), "r"(b1))

// convert one K-float4 + one V-float4 chunk into buffer at base_nxt
__device__ __forceinline__ void conv_chunk(char* smem, u32 base_nxt, int idx,
                                           float4 kreg, float4 vreg) {
    int row = idx >> 5, col0 = (idx & 31) * 4;
    u32 a = swz(row, col0, 3);
    u32 h0, l0, h1, l1;
    split2(kreg.x, kreg.y, h0, l0);
    split2(kreg.z, kreg.w, h1, l1);
    *(uint2*)(smem + base_nxt + OFF_KHI + a) = make_uint2(h0, h1);
    *(uint2*)(smem + base_nxt + OFF_KLO + a) = make_uint2(l0, l1);
    split2(vreg.x, vreg.y, h0, l0);
    split2(vreg.z, vreg.w, h1, l1);
    *(uint2*)(smem + base_nxt + OFF_VHI + a) = make_uint2(h0, h1);
    *(uint2*)(smem + base_nxt + OFF_VLO + a) = make_uint2(l0, l1);
}

__global__ __launch_bounds__(NTH, 1)
void fa_mma_kernel(const float* __restrict__ Qg, const float* __restrict__ Kg,
                   const float* __restrict__ Vg, float* __restrict__ Og) {
    extern __shared__ char smem[];
    const u32 sb = smem_u32(smem);
    const int tid = threadIdx.x, wid = tid >> 5, lane = tid & 31;

    const size_t hoff = (size_t)blockIdx.y * SEQ * DD;
    const float* Qh = Qg + hoff + (size_t)blockIdx.x * BM * DD;
    const float* Kh = Kg + hoff;
    const float* Vh = Vg + hoff;
    float*       Oh = Og + hoff + (size_t)blockIdx.x * BM * DD;

    // ---- prologue: Q (scale folded) + K0/V0 into buffer 0 ----
    {
        const float4* G4 = (const float4*)Qh;
        #pragma unroll
        for (int t = 0; t < 16; t++) {
            int i = tid + t * NTH;
            int row = i >> 5, col0 = (i & 31) * 4;
            float4 v = G4[i];
            v.x *= SCALE_INV; v.y *= SCALE_INV; v.z *= SCALE_INV; v.w *= SCALE_INV;
            u32 h0, l0, h1, l1;
            split2(v.x, v.y, h0, l0);
            split2(v.z, v.w, h1, l1);
            u32 a = swz(row, col0, 4);
            *(uint2*)(smem + SM_QHI + a) = make_uint2(h0, h1);
            *(uint2*)(smem + SM_QLO + a) = make_uint2(l0, l1);
        }
        const float4* K4 = (const float4*)Kh;
        const float4* V4 = (const float4*)Vh;
        #pragma unroll
        for (int t = 0; t < 8; t++) {
            int i = tid + t * NTH;
            conv_chunk(smem, SM_KV, i, K4[i], V4[i]);
        }
        __syncthreads();
    }

    float oacc[16][4];
    #pragma unroll
    for (int n = 0; n < 16; n++)
        #pragma unroll
        for (int c = 0; c < 4; c++) oacc[n][c] = 0.0f;

    float m0 = -1e30f, m1 = -1e30f, l0s = 0.0f, l1s = 0.0f;

    const int frow  = (lane & 7) + ((lane >> 3) & 1) * 8;
    const int fcol8 = ((lane >> 4) & 1) * 8;
    const int qrow  = wid * 16 + frow;

    for (int kt = 0; kt < NT; kt++) {
        const u32 bcur = SM_KV + (u32)(kt & 1) * KV_STRIDE;
        const u32 bnxt = SM_KV + (u32)((kt & 1) ^ 1) * KV_STRIDE;
        const bool pf = (kt + 1 < NT);
        const float4* K4n = (const float4*)(Kh + (size_t)(kt + 1) * BN * DD);
        const float4* V4n = (const float4*)(Vh + (size_t)(kt + 1) * BN * DD);

        // ---- S = Q K^T : double-buffered K frags ----
        float sacc[8][4];
        #pragma unroll
        for (int j = 0; j < 8; j++)
            #pragma unroll
            for (int c = 0; c < 4; c++) sacc[j][c] = 0.0f;

        {
            u32 ah[4], al[4], bh[2][4], bl[2][4];
            {
                u32 qa = sb + SM_QHI + swz(qrow, fcol8, 4);
                LDSM4(ah, qa);
                LDSM4(al, qa + (SM_QLO - SM_QHI));
                u32 ka = sb + bcur + OFF_KHI + swz(frow, fcol8, 3);
                LDSM4(bh[0], ka);
                LDSM4(bl[0], ka + (OFF_KLO - OFF_KHI));
            }
            #pragma unroll
            for (int kk = 0; kk < 8; kk++) {
                #pragma unroll
                for (int ng = 0; ng < 4; ng++) {
                    int cur = ng & 1, nxt = cur ^ 1;
                    if (ng < 3) {
                        u32 ka = sb + bcur + OFF_KHI + swz((ng + 1) * 16 + frow, kk * 16 + fcol8, 3);
                        LDSM4(bh[nxt], ka);
                        LDSM4(bl[nxt], ka + (OFF_KLO - OFF_KHI));
                    } else if (kk < 7) {
                        u32 ka = sb + bcur + OFF_KHI + swz(frow, (kk + 1) * 16 + fcol8, 3);
                        LDSM4(bh[nxt], ka);
                        LDSM4(bl[nxt], ka + (OFF_KLO - OFF_KHI));
                    }
                    MMA(sacc[2 * ng],     ah, bh[cur][0], bh[cur][2]);
                    MMA(sacc[2 * ng],     al, bh[cur][0], bh[cur][2]);
                    MMA(sacc[2 * ng],     ah, bl[cur][0], bl[cur][2]);
                    MMA(sacc[2 * ng + 1], ah, bh[cur][1], bh[cur][3]);
                    MMA(sacc[2 * ng + 1], al, bh[cur][1], bh[cur][3]);
                    MMA(sacc[2 * ng + 1], ah, bl[cur][1], bl[cur][3]);
                }
                if (kk < 7) {
                    u32 qa = sb + SM_QHI + swz(qrow, (kk + 1) * 16 + fcol8, 4);
                    LDSM4(ah, qa);
                    LDSM4(al, qa + (SM_QLO - SM_QHI));
                }
            }
        }

        // ---- online softmax (scale pre-folded into Q) ----
        float mx0 = m0, mx1 = m1;
        #pragma unroll
        for (int j = 0; j < 8; j++) {
            mx0 = fmaxf(mx0, fmaxf(sacc[j][0], sacc[j][1]));
            mx1 = fmaxf(mx1, fmaxf(sacc[j][2], sacc[j][3]));
        }
        mx0 = fmaxf(mx0, __shfl_xor_sync(0xffffffffu, mx0, 1));
        mx0 = fmaxf(mx0, __shfl_xor_sync(0xffffffffu, mx0, 2));
        mx1 = fmaxf(mx1, __shfl_xor_sync(0xffffffffu, mx1, 1));
        mx1 = fmaxf(mx1, __shfl_xor_sync(0xffffffffu, mx1, 2));
        float alpha0 = __expf(m0 - mx0);
        float alpha1 = __expf(m1 - mx1);

        float sum0 = 0.0f, sum1 = 0.0f;
        u32 ph[8][2], pl[8][2];
        #pragma unroll
        for (int j = 0; j < 8; j++) {
            float p0 = __expf(sacc[j][0] - mx0);
            float p1 = __expf(sacc[j][1] - mx0);
            float p2 = __expf(sacc[j][2] - mx1);
            float p3 = __expf(sacc[j][3] - mx1);
            sum0 += p0 + p1;
            sum1 += p2 + p3;
            split2(p0, p1, ph[j][0], pl[j][0]);
            split2(p2, p3, ph[j][1], pl[j][1]);
        }
        sum0 += __shfl_xor_sync(0xffffffffu, sum0, 1);
        sum0 += __shfl_xor_sync(0xffffffffu, sum0, 2);
        sum1 += __shfl_xor_sync(0xffffffffu, sum1, 1);
        sum1 += __shfl_xor_sync(0xffffffffu, sum1, 2);
        l0s = l0s * alpha0 + sum0;
        l1s = l1s * alpha1 + sum1;
        m0 = mx0; m1 = mx1;

        #pragma unroll
        for (int n = 0; n < 16; n++) {
            oacc[n][0] *= alpha0; oacc[n][1] *= alpha0;
            oacc[n][2] *= alpha1; oacc[n][3] *= alpha1;
        }

        // ---- O += P V, with LDG prefetch chunks interleaved ----
        {
            float4 kreg, vreg;
            u32 vh[2][4], vl[2][4];
            {
                u32 va = sb + bcur + OFF_VHI + swz(frow, fcol8, 3);
                LDSM4T(vh[0], va);
                LDSM4T(vl[0], va + (OFF_VLO - OFF_VHI));
            }
            #pragma unroll
            for (int kk = 0; kk < 4; kk++) {
                u32 pah[4] = {ph[2*kk][0], ph[2*kk][1], ph[2*kk+1][0], ph[2*kk+1][1]};
                u32 pal[4] = {pl[2*kk][0], pl[2*kk][1], pl[2*kk+1][0], pl[2*kk+1][1]};
                #pragma unroll
                for (int ng = 0; ng < 8; ng++) {
                    int u = kk * 8 + ng;
                    if ((u & 3) == 0) {
                        int c = u >> 2;                  // chunk 0..7
                        if (pf) {
                            if (c > 0) conv_chunk(smem, bnxt, tid + (c - 1) * NTH, kreg, vreg);
                            int i = tid + c * NTH;
                            kreg = K4n[i];
                            vreg = V4n[i];
                        }
                    }
                    int cur = u & 1, nxt = cur ^ 1;
                    if (u < 31) {
                        int u1 = u + 1;
                        u32 va = sb + bcur + OFF_VHI + swz((u1 >> 3) * 16 + frow, (u1 & 7) * 16 + fcol8, 3);
                        LDSM4T(vh[nxt], va);
                        LDSM4T(vl[nxt], va + (OFF_VLO - OFF_VHI));
                    }
                    MMA(oacc[2*ng],     pah, vh[cur][0], vh[cur][1]);
                    MMA(oacc[2*ng],     pal, vh[cur][0], vh[cur][1]);
                    MMA(oacc[2*ng],     pah, vl[cur][0], vl[cur][1]);
                    MMA(oacc[2*ng + 1], pah, vh[cur][2], vh[cur][3]);
                    MMA(oacc[2*ng + 1], pal, vh[cur][2], vh[cur][3]);
                    MMA(oacc[2*ng + 1], pah, vl[cur][2], vl[cur][3]);
                }
            }
            if (pf) conv_chunk(smem, bnxt, tid + 7 * NTH, kreg, vreg);
        }

        __syncthreads();   // buffer handoff: bnxt complete, bcur reads done
    }

    // ---- epilogue ----
    float inv0 = 1.0f / l0s, inv1 = 1.0f / l1s;
    int orow0 = wid * 16 + (lane >> 2);
    int orow1 = orow0 + 8;
    #pragma unroll
    for (int n = 0; n < 16; n++) {
        int col = n * 8 + 2 * (lane & 3);
        *(float2*)(Oh + (size_t)orow0 * DD + col) = make_float2(oacc[n][0] * inv0, oacc[n][1] * inv0);
        *(float2*)(Oh + (size_t)orow1 * DD + col) = make_float2(oacc[n][2] * inv1, oacc[n][3] * inv1);
    }
}

extern "C" void kernel_launch(void* const* d_in, const int* in_sizes, int n_in,
                              void* d_out, int out_size) {
    const float* Q = (const float*)d_in[0];
    const float* K = (const float*)d_in[1];
    const float* V = (const float*)d_in[2];
    float* O = (float*)d_out;

    cudaFuncSetAttribute(fa_mma_kernel,
                         cudaFuncAttributeMaxDynamicSharedMemorySize, SM_TOTAL);

    dim3 grid(SEQ / BM, 64 /* B*H */);
    fa_mma_kernel<<<grid, NTH, SM_TOTAL>>>(Q, K, V, O);
}